// round 10
// baseline (speedup 1.0000x reference)
#include <cuda_runtime.h>

// Reference semantics: image (B,M,N,2) raw-reinterpreted as (2B,M,N) planes;
// flow2[p] = flow[p>>1]; out[p*MN + y*N + x] = bilinear(plane p, x+dx, y+dy),
// zero outside bounds.
// Design: block = 4 rows of one batch, blockDim=384 (x = threadIdx.x).
// Stage a 13-row window [y0-4, y0+8] of BOTH planes into SMEM (edge-clamped,
// coalesced float4), then bilinear-gather from SMEM (LDS). Samples whose
// corner rows fall outside the window (P ~ 6e-5 for N(0,1) flow) take a
// global-memory fallback identical to the baseline — exact same results.

#define MM 384
#define NN 384
#define MN (MM * NN)
#define ROWS 4
#define HALO 4
#define NSTAGE 13            // ROWS + 2*HALO + 1
#define STR 388              // padded row stride (words): float4-alignable, bank-shift 4/row

__global__ __launch_bounds__(384) void warp_kernel(
    const float*  __restrict__ image,  // 2B*MN floats (raw)
    const float2* __restrict__ flow,   // B*MN float2
    float*        __restrict__ out)    // 2B*MN floats (raw)
{
    __shared__ float sbuf[2][NSTAGE][STR];   // 40,352 B

    int bid = blockIdx.x;
    int b   = bid / 96;
    int y0  = (bid - b * 96) * ROWS;
    int tid = threadIdx.x;
    int ybase = y0 - HALO;

    const size_t pbase = (size_t)(2 * b) * MN;
    const float* pA = image + pbase;
    const float* pB = pA + MN;

    // ---- stage 13 rows x 96 float4 x 2 planes = 2496 float4, coalesced ----
    for (int i = tid; i < 2 * NSTAGE * 96; i += 384) {
        int p   = i / (NSTAGE * 96);
        int rem = i - p * (NSTAGE * 96);
        int r   = rem / 96;
        int c4  = rem - r * 96;
        int sr  = min(max(ybase + r, 0), MM - 1);     // edge-clamped row
        const float* src = (p ? pB : pA) + sr * NN + c4 * 4;
        float4 v = __ldg((const float4*)src);
        *(float4*)&sbuf[p][r][c4 * 4] = v;
    }
    __syncthreads();

    // ---- per-thread: 4 pixels (same x, rows y0..y0+3), both planes ----
    int x = tid;
    const float2* frow = flow + (size_t)b * MN + y0 * NN + x;

    float2 f[ROWS];
#pragma unroll
    for (int i = 0; i < ROWS; i++)
        f[i] = __ldcs(frow + i * NN);

    float* oA = out + pbase + y0 * NN + x;
    float* oB = oA + MN;

#pragma unroll
    for (int i = 0; i < ROWS; i++) {
        float xs = (float)x + f[i].x;
        float ys = (float)(y0 + i) + f[i].y;

        float x0f = floorf(xs);
        float y0f = floorf(ys);
        float wx = xs - x0f;
        float wy = ys - y0f;
        int xi0 = (int)x0f;
        int yi0 = (int)y0f;
        int xi1 = xi0 + 1;
        int yi1 = yi0 + 1;

        float wxm0 = ((unsigned)xi0 < (unsigned)NN) ? (1.0f - wx) : 0.0f;
        float wxm1 = ((unsigned)xi1 < (unsigned)NN) ? wx : 0.0f;
        float wym0 = ((unsigned)yi0 < (unsigned)MM) ? (1.0f - wy) : 0.0f;
        float wym1 = ((unsigned)yi1 < (unsigned)MM) ? wy : 0.0f;

        int xc0 = min(max(xi0, 0), NN - 1);
        int xc1 = min(max(xi1, 0), NN - 1);
        int yc0 = min(max(yi0, 0), MM - 1);
        int yc1 = min(max(yi1, 0), MM - 1);

        float w00 = wym0 * wxm0;
        float w01 = wym0 * wxm1;
        float w10 = wym1 * wxm0;
        float w11 = wym1 * wxm1;

        int r0 = yc0 - ybase;
        int r1 = yc1 - ybase;
        bool inwin = ((unsigned)r0 < (unsigned)NSTAGE) &
                     ((unsigned)r1 < (unsigned)NSTAGE);

        float vA00, vA01, vA10, vA11, vB00, vB01, vB10, vB11;
        if (inwin) {
            // SMEM gathers (common path)
            vA00 = sbuf[0][r0][xc0];  vA01 = sbuf[0][r0][xc1];
            vA10 = sbuf[0][r1][xc0];  vA11 = sbuf[0][r1][xc1];
            vB00 = sbuf[1][r0][xc0];  vB01 = sbuf[1][r0][xc1];
            vB10 = sbuf[1][r1][xc0];  vB11 = sbuf[1][r1][xc1];
        } else {
            // rare global fallback (|dy| beyond halo) — identical to baseline
            int g00 = yc0 * NN + xc0, g01 = yc0 * NN + xc1;
            int g10 = yc1 * NN + xc0, g11 = yc1 * NN + xc1;
            vA00 = __ldg(pA + g00);  vA01 = __ldg(pA + g01);
            vA10 = __ldg(pA + g10);  vA11 = __ldg(pA + g11);
            vB00 = __ldg(pB + g00);  vB01 = __ldg(pB + g01);
            vB10 = __ldg(pB + g10);  vB11 = __ldg(pB + g11);
        }

        float accA = vA00 * w00 + vA01 * w01 + vA10 * w10 + vA11 * w11;
        float accB = vB00 * w00 + vB01 * w01 + vB10 * w10 + vB11 * w11;

        __stcs(oA + i * NN, accA);
        __stcs(oB + i * NN, accB);
    }
}

extern "C" void kernel_launch(void* const* d_in, const int* in_sizes, int n_in,
                              void* d_out, int out_size)
{
    const float*  image = (const float*)d_in[0];
    const float2* flow  = (const float2*)d_in[1];
    float* out = (float*)d_out;

    int B = out_size / (2 * MN);
    int blocks = B * (MM / ROWS);   // 64 * 96 = 6144
    warp_kernel<<<blocks, 384>>>(image, flow, out);
}